// round 10
// baseline (speedup 1.0000x reference)
#include <cuda_runtime.h>
#include <cuda_fp16.h>

// ---------------- constants (match problem shape) ----------------
#define NMAX      100000
#define NNZMAX    3200000
#define DIMC      256

// ---------------- device scratch (no allocations allowed) ----------------
__device__ static float  g_Hn[NMAX * DIMC];   // SpMM result per hop (fp32)
__device__ static float  g_HA[NMAX * DIMC];   // H after hop 0 (fp32, GEMM Hc)
__device__ static float  g_HB[NMAX * DIMC];   // H after hop 1
__device__ static __half g_H16[NMAX * DIMC];  // fp16 shadow of current H (SpMM gather)
__device__ static int2   g_edges[NNZMAX];     // CSR: (col, val-as-bits) sorted by row
__device__ static int    g_cnt[NMAX];
__device__ static int    g_rowptr[NMAX + 1];
__device__ static int    g_woff[NMAX];

// ---------------- CSR build ----------------
__global__ void zero_cnt_kernel(int* cnt, int N) {
    int i = blockIdx.x * blockDim.x + threadIdx.x;
    if (i < N) cnt[i] = 0;
}

// 4 edges per thread: vector load + 4 independent atomics (MLP)
__global__ void hist_kernel(const int* __restrict__ rows, int* cnt, int nnz) {
    int e = (blockIdx.x * blockDim.x + threadIdx.x) * 4;
    if (e + 4 <= nnz) {
        int4 r = *(const int4*)(rows + e);
        atomicAdd(&cnt[r.x], 1);
        atomicAdd(&cnt[r.y], 1);
        atomicAdd(&cnt[r.z], 1);
        atomicAdd(&cnt[r.w], 1);
    } else {
        for (int k = e; k < nnz; k++) atomicAdd(&cnt[rows[k]], 1);
    }
}

// single-block exclusive scan over N counts (1024 threads, sequential chunks)
__global__ void scan_kernel(const int* __restrict__ cnt, int* row_ptr, int* woff,
                            int N, int nnz) {
    __shared__ int wsum[32];
    int tid = threadIdx.x;
    int CH = (N + 1023) / 1024;
    int base = tid * CH;
    int s = 0;
    for (int j = 0; j < CH; j++) {
        int i = base + j;
        if (i < N) s += cnt[i];
    }
    int v = s;
    #pragma unroll
    for (int d = 1; d < 32; d <<= 1) {
        int n = __shfl_up_sync(0xffffffffu, v, d);
        if ((tid & 31) >= d) v += n;
    }
    if ((tid & 31) == 31) wsum[tid >> 5] = v;
    __syncthreads();
    if (tid < 32) {
        int w = wsum[tid];
        #pragma unroll
        for (int d = 1; d < 32; d <<= 1) {
            int n = __shfl_up_sync(0xffffffffu, w, d);
            if (tid >= d) w += n;
        }
        wsum[tid] = w;
    }
    __syncthreads();
    int warp = tid >> 5;
    int excl = (v - s) + (warp > 0 ? wsum[warp - 1] : 0);
    int run = excl;
    for (int j = 0; j < CH; j++) {
        int i = base + j;
        if (i < N) {
            row_ptr[i] = run;
            woff[i]    = run;
            run += cnt[i];
        }
    }
    if (tid == 0) row_ptr[N] = nnz;
}

// 4 edges per thread: vector loads, 4 independent atomic+store pairs
__global__ void scatter_kernel(const int* __restrict__ rows,
                               const int* __restrict__ cols,
                               const float* __restrict__ vals,
                               int* woff, int2* edges, int nnz) {
    int e = (blockIdx.x * blockDim.x + threadIdx.x) * 4;
    if (e + 4 <= nnz) {
        int4   r = *(const int4*)(rows + e);
        int4   c = *(const int4*)(cols + e);
        float4 v = *(const float4*)(vals + e);
        int p0 = atomicAdd(&woff[r.x], 1);
        int p1 = atomicAdd(&woff[r.y], 1);
        int p2 = atomicAdd(&woff[r.z], 1);
        int p3 = atomicAdd(&woff[r.w], 1);
        edges[p0] = make_int2(c.x, __float_as_int(v.x));
        edges[p1] = make_int2(c.y, __float_as_int(v.y));
        edges[p2] = make_int2(c.z, __float_as_int(v.z));
        edges[p3] = make_int2(c.w, __float_as_int(v.w));
    } else {
        for (int k = e; k < nnz; k++) {
            int p = atomicAdd(&woff[rows[k]], 1);
            edges[p] = make_int2(cols[k], __float_as_int(vals[k]));
        }
    }
}

// ---------------- fp32 -> fp16 conversion (for the initial m) ----------------
__global__ void f2h_kernel(const float* __restrict__ src, __half* __restrict__ dst,
                           int n) {  // n = total elems / 2
    int i = blockIdx.x * blockDim.x + threadIdx.x;
    if (i < n) {
        float2 v = ((const float2*)src)[i];
        ((__half2*)dst)[i] = __floats2half2_rn(v.x, v.y);
    }
}

// ---------------- SpMM: warp per row, CSR, fp16 gather, 4-edge MLP ---------
__global__ void spmm16_kernel(const __half* __restrict__ H,
                              const int* __restrict__ row_ptr,
                              const int2* __restrict__ edges,
                              float* __restrict__ Hn, int N) {
    int warp = (blockIdx.x * blockDim.x + threadIdx.x) >> 5;
    int lane = threadIdx.x & 31;
    if (warp >= N) return;
    int start = row_ptr[warp];
    int end   = row_ptr[warp + 1];

    float acc[8];
    #pragma unroll
    for (int i = 0; i < 8; i++) acc[i] = 0.f;

    auto accum = [&](uint4 raw, float val) {
        const __half2* hh = (const __half2*)&raw;
        float2 f0 = __half22float2(hh[0]);
        float2 f1 = __half22float2(hh[1]);
        float2 f2 = __half22float2(hh[2]);
        float2 f3 = __half22float2(hh[3]);
        acc[0] += val * f0.x; acc[1] += val * f0.y;
        acc[2] += val * f1.x; acc[3] += val * f1.y;
        acc[4] += val * f2.x; acc[5] += val * f2.y;
        acc[6] += val * f3.x; acc[7] += val * f3.y;
    };

    for (int e0 = start; e0 < end; e0 += 32) {
        int idx = e0 + lane;
        int2 ed = make_int2(0, 0);
        if (idx < end) ed = edges[idx];
        int cnt = min(32, end - e0);
        int j = 0;
        for (; j + 4 <= cnt; j += 4) {
            int   c0 = __shfl_sync(0xffffffffu, ed.x, j + 0);
            int   c1 = __shfl_sync(0xffffffffu, ed.x, j + 1);
            int   c2 = __shfl_sync(0xffffffffu, ed.x, j + 2);
            int   c3 = __shfl_sync(0xffffffffu, ed.x, j + 3);
            float v0 = __int_as_float(__shfl_sync(0xffffffffu, ed.y, j + 0));
            float v1 = __int_as_float(__shfl_sync(0xffffffffu, ed.y, j + 1));
            float v2 = __int_as_float(__shfl_sync(0xffffffffu, ed.y, j + 2));
            float v3 = __int_as_float(__shfl_sync(0xffffffffu, ed.y, j + 3));
            uint4 r0 = ((const uint4*)(H + (size_t)c0 * DIMC))[lane];
            uint4 r1 = ((const uint4*)(H + (size_t)c1 * DIMC))[lane];
            uint4 r2 = ((const uint4*)(H + (size_t)c2 * DIMC))[lane];
            uint4 r3 = ((const uint4*)(H + (size_t)c3 * DIMC))[lane];
            accum(r0, v0);
            accum(r1, v1);
            accum(r2, v2);
            accum(r3, v3);
        }
        for (; j < cnt; j++) {
            int   col = __shfl_sync(0xffffffffu, ed.x, j);
            float val = __int_as_float(__shfl_sync(0xffffffffu, ed.y, j));
            uint4 raw = ((const uint4*)(H + (size_t)col * DIMC))[lane];
            accum(raw, val);
        }
    }
    float4* out = (float4*)(Hn + (size_t)warp * DIMC);
    out[lane * 2 + 0] = make_float4(acc[0], acc[1], acc[2], acc[3]);
    out[lane * 2 + 1] = make_float4(acc[4], acc[5], acc[6], acc[7]);
}

// ---------------- tf32 tensor-core GEMM, full-N tile ----------------
// out[M,256] = Hn@Wn^T + Hc@Ws^T + (bn+bs), optional ELU.
// One CTA = 128 rows x 256 cols (FULL N): A slab loaded ONCE (was twice with
// 2 col-blocks). 256 threads, 8 warps (2M x 4N), warp tile 64x64, BK=16,
// cp.async double-buffered dynamic smem.
#define GSTR 20   // smem row stride in words (16 k + 4 pad) -> conflict-free frags
#define SM_GEMM ((2 * 128 * GSTR + 2 * 256 * GSTR) * 4)   // 61440 B

__device__ __forceinline__ unsigned f2tf32(float x) {
    unsigned r;
    asm("cvt.rna.tf32.f32 %0, %1;" : "=r"(r) : "f"(x));
    return r;
}

__global__ __launch_bounds__(256, 1)
void gemm_tf32_kernel(const float* __restrict__ Hn, const float* __restrict__ Hc,
                      const float* __restrict__ Wn, const float* __restrict__ Ws,
                      const float* __restrict__ bn, const float* __restrict__ bs,
                      float* __restrict__ out, __half* __restrict__ out16,
                      int M, int doElu) {
    extern __shared__ float sm[];
    float* As = sm;                        // [2][128*GSTR]
    float* Bs = sm + 2 * 128 * GSTR;       // [2][256*GSTR]

    int tid  = threadIdx.x;
    int lane = tid & 31;
    int wid  = tid >> 5;
    int grp  = lane >> 2;       // 0..7
    int tig  = lane & 3;        // 0..3
    int warpM = wid >> 2;       // 0..1  (64-row slice)
    int warpN = wid & 3;        // 0..3  (64-col slice)
    int rowBase = blockIdx.x * 128;

    int lf = tid & 3;           // k-float4 slot (0..3 -> k 0..15)
    int lr = tid >> 2;          // 0..63 row base

    float c[4][8][4];
    #pragma unroll
    for (int mi = 0; mi < 4; mi++)
        #pragma unroll
        for (int ni = 0; ni < 8; ni++)
            #pragma unroll
            for (int r = 0; r < 4; r++) c[mi][ni][r] = 0.f;

    // issue cp.async loads for k-slab `it` into stage it&1
    auto issue = [&](int it) {
        int k0 = it * 16;
        const float* Asrc = (k0 < 256) ? Hn : Hc;
        const float* Wsrc = (k0 < 256) ? Wn : Ws;
        int kOff = k0 & 255;
        int st = it & 1;
        // A tile: 128 rows x 16 k (512 float4 chunks / 256 threads = 2)
        #pragma unroll
        for (int i = 0; i < 2; i++) {
            int row = lr + 64 * i;
            int grow = rowBase + row;
            int ok = (grow < M);
            const float* asrc = Asrc + (size_t)(ok ? grow : 0) * DIMC + kOff + lf * 4;
            unsigned adst = (unsigned)__cvta_generic_to_shared(
                &As[st * 128 * GSTR + row * GSTR + lf * 4]);
            int asz = ok ? 16 : 0;
            asm volatile("cp.async.cg.shared.global [%0], [%1], 16, %2;\n"
                         :: "r"(adst), "l"(asrc), "r"(asz));
        }
        // B tile: 256 rows (C cols) x 16 k (1024 float4 chunks / 256 threads = 4)
        #pragma unroll
        for (int i = 0; i < 4; i++) {
            int row = lr + 64 * i;
            const float* bsrc = Wsrc + (size_t)row * DIMC + kOff + lf * 4;
            unsigned bdst = (unsigned)__cvta_generic_to_shared(
                &Bs[st * 256 * GSTR + row * GSTR + lf * 4]);
            asm volatile("cp.async.cg.shared.global [%0], [%1], 16, %2;\n"
                         :: "r"(bdst), "l"(bsrc), "r"(16));
        }
        asm volatile("cp.async.commit_group;\n");
    };

    issue(0);

    for (int it = 0; it < 32; it++) {
        if (it + 1 < 32) {
            issue(it + 1);
            asm volatile("cp.async.wait_group 1;\n");
        } else {
            asm volatile("cp.async.wait_group 0;\n");
        }
        __syncthreads();

        const float* Ast = As + (it & 1) * 128 * GSTR;
        const float* Bst = Bs + (it & 1) * 256 * GSTR;
        #pragma unroll
        for (int kk = 0; kk < 2; kk++) {
            unsigned a[4][4], b[8][2];
            int k = kk * 8 + tig;
            #pragma unroll
            for (int mi = 0; mi < 4; mi++) {
                int m0 = warpM * 64 + mi * 16 + grp;
                a[mi][0] = f2tf32(Ast[m0 * GSTR + k]);
                a[mi][1] = f2tf32(Ast[(m0 + 8) * GSTR + k]);
                a[mi][2] = f2tf32(Ast[m0 * GSTR + k + 4]);
                a[mi][3] = f2tf32(Ast[(m0 + 8) * GSTR + k + 4]);
            }
            #pragma unroll
            for (int ni = 0; ni < 8; ni++) {
                int n0 = warpN * 64 + ni * 8 + grp;
                b[ni][0] = f2tf32(Bst[n0 * GSTR + k]);
                b[ni][1] = f2tf32(Bst[n0 * GSTR + k + 4]);
            }
            #pragma unroll
            for (int mi = 0; mi < 4; mi++)
                #pragma unroll
                for (int ni = 0; ni < 8; ni++) {
                    asm volatile(
                        "mma.sync.aligned.m16n8k8.row.col.f32.tf32.tf32.f32 "
                        "{%0,%1,%2,%3}, {%4,%5,%6,%7}, {%8,%9}, {%0,%1,%2,%3};\n"
                        : "+f"(c[mi][ni][0]), "+f"(c[mi][ni][1]),
                          "+f"(c[mi][ni][2]), "+f"(c[mi][ni][3])
                        : "r"(a[mi][0]), "r"(a[mi][1]), "r"(a[mi][2]), "r"(a[mi][3]),
                          "r"(b[ni][0]), "r"(b[ni][1]));
                }
        }
        __syncthreads();
    }

    // epilogue: bias + optional ELU (+ fp16 shadow for next SpMM)
    #pragma unroll
    for (int mi = 0; mi < 4; mi++) {
        #pragma unroll
        for (int r = 0; r < 2; r++) {
            int grow = rowBase + warpM * 64 + mi * 16 + grp + r * 8;
            if (grow >= M) continue;
            #pragma unroll
            for (int ni = 0; ni < 8; ni++) {
                int gcol = warpN * 64 + ni * 8 + tig * 2;
                float v0 = c[mi][ni][r * 2 + 0] + bn[gcol]     + bs[gcol];
                float v1 = c[mi][ni][r * 2 + 1] + bn[gcol + 1] + bs[gcol + 1];
                if (doElu) {
                    if (v0 < 0.f) v0 = expm1f(v0);
                    if (v1 < 0.f) v1 = expm1f(v1);
                }
                *(float2*)(out + (size_t)grow * DIMC + gcol) = make_float2(v0, v1);
                if (out16)
                    *(__half2*)(out16 + (size_t)grow * DIMC + gcol) =
                        __floats2half2_rn(v0, v1);
            }
        }
    }
}

// ---------------- launch ----------------
extern "C" void kernel_launch(void* const* d_in, const int* in_sizes, int n_in,
                              void* d_out, int out_size) {
    const float* m    = (const float*)d_in[0];
    const float* vals = (const float*)d_in[1];
    const float* Wn   = (const float*)d_in[2];
    const float* bn   = (const float*)d_in[3];
    const float* Ws   = (const float*)d_in[4];
    const float* bs   = (const float*)d_in[5];
    const int*   rows = (const int*)d_in[6];   // int32: JAX default x64-disabled
    const int*   cols = (const int*)d_in[7];

    int N    = in_sizes[0] / DIMC;
    int nnz  = in_sizes[1];
    int hops = in_sizes[2] / (DIMC * DIMC);

    float *Hn, *HA, *HB;
    __half* H16;
    int *cnt, *rowptr, *woff;
    int2* edges;
    cudaGetSymbolAddress((void**)&Hn,     g_Hn);
    cudaGetSymbolAddress((void**)&HA,     g_HA);
    cudaGetSymbolAddress((void**)&HB,     g_HB);
    cudaGetSymbolAddress((void**)&H16,    g_H16);
    cudaGetSymbolAddress((void**)&edges,  g_edges);
    cudaGetSymbolAddress((void**)&cnt,    g_cnt);
    cudaGetSymbolAddress((void**)&rowptr, g_rowptr);
    cudaGetSymbolAddress((void**)&woff,   g_woff);

    cudaFuncSetAttribute(gemm_tf32_kernel,
                         cudaFuncAttributeMaxDynamicSharedMemorySize, SM_GEMM);

    // --- build CSR once, reuse across hops ---
    zero_cnt_kernel<<<(N + 255) / 256, 256>>>(cnt, N);
    int e4 = (nnz + 3) / 4;
    hist_kernel<<<(e4 + 255) / 256, 256>>>(rows, cnt, nnz);
    scan_kernel<<<1, 1024>>>(cnt, rowptr, woff, N, nnz);
    scatter_kernel<<<(e4 + 255) / 256, 256>>>(rows, cols, vals, woff, edges, nnz);

    // --- fp16 shadow of initial H ---
    int nh2 = N * DIMC / 2;
    f2h_kernel<<<(nh2 + 255) / 256, 256>>>(m, H16, nh2);

    // --- hop loop ---
    float* out0 = (float*)d_out;
    int spmm_blocks = (N * 32 + 255) / 256;     // warp per row
    int ggrid = (N + 127) / 128;

    const float* Hcur = m;
    for (int i = 0; i < hops; i++) {
        spmm16_kernel<<<spmm_blocks, 256>>>(H16, rowptr, edges, Hn, N);
        int last = (i == hops - 1);
        float* dst = last ? out0 : (i == 0 ? HA : HB);
        gemm_tf32_kernel<<<ggrid, 256, SM_GEMM>>>(Hn, Hcur,
                                         Wn + (size_t)i * DIMC * DIMC,
                                         Ws + (size_t)i * DIMC * DIMC,
                                         bn + (size_t)i * DIMC,
                                         bs + (size_t)i * DIMC,
                                         dst, last ? (__half*)nullptr : H16,
                                         N, !last);
        Hcur = dst;
    }
}

// round 11
// speedup vs baseline: 1.0312x; 1.0312x over previous
#include <cuda_runtime.h>
#include <cuda_fp16.h>

// ---------------- constants (match problem shape) ----------------
#define NMAX      100000
#define NNZMAX    3200000
#define DIMC      256

// ---------------- device scratch (no allocations allowed) ----------------
__device__ static float  g_Hn[NMAX * DIMC];   // SpMM result per hop (fp32)
__device__ static float  g_P [NMAX * DIMC];   // partial H@Ws^T per hop (fp32)
__device__ static float  g_HA[NMAX * DIMC];   // H after hop 0
__device__ static float  g_HB[NMAX * DIMC];   // H after hop 1
__device__ static __half g_H16[NMAX * DIMC];  // fp16 shadow of current H (SpMM gather)
__device__ static int2   g_edges[NNZMAX];     // CSR: (col, val-as-bits) sorted by row
__device__ static int    g_cnt[NMAX];
__device__ static int    g_rowptr[NMAX + 1];
__device__ static int    g_woff[NMAX];

// ---------------- CSR build ----------------
__global__ void zero_cnt_kernel(int* cnt, int N) {
    int i = blockIdx.x * blockDim.x + threadIdx.x;
    if (i < N) cnt[i] = 0;
}

__global__ void hist_kernel(const int* __restrict__ rows, int* cnt, int nnz) {
    int e = (blockIdx.x * blockDim.x + threadIdx.x) * 4;
    if (e + 4 <= nnz) {
        int4 r = *(const int4*)(rows + e);
        atomicAdd(&cnt[r.x], 1);
        atomicAdd(&cnt[r.y], 1);
        atomicAdd(&cnt[r.z], 1);
        atomicAdd(&cnt[r.w], 1);
    } else {
        for (int k = e; k < nnz; k++) atomicAdd(&cnt[rows[k]], 1);
    }
}

__global__ void scan_kernel(const int* __restrict__ cnt, int* row_ptr, int* woff,
                            int N, int nnz) {
    __shared__ int wsum[32];
    int tid = threadIdx.x;
    int CH = (N + 1023) / 1024;
    int base = tid * CH;
    int s = 0;
    for (int j = 0; j < CH; j++) {
        int i = base + j;
        if (i < N) s += cnt[i];
    }
    int v = s;
    #pragma unroll
    for (int d = 1; d < 32; d <<= 1) {
        int n = __shfl_up_sync(0xffffffffu, v, d);
        if ((tid & 31) >= d) v += n;
    }
    if ((tid & 31) == 31) wsum[tid >> 5] = v;
    __syncthreads();
    if (tid < 32) {
        int w = wsum[tid];
        #pragma unroll
        for (int d = 1; d < 32; d <<= 1) {
            int n = __shfl_up_sync(0xffffffffu, w, d);
            if (tid >= d) w += n;
        }
        wsum[tid] = w;
    }
    __syncthreads();
    int warp = tid >> 5;
    int excl = (v - s) + (warp > 0 ? wsum[warp - 1] : 0);
    int run = excl;
    for (int j = 0; j < CH; j++) {
        int i = base + j;
        if (i < N) {
            row_ptr[i] = run;
            woff[i]    = run;
            run += cnt[i];
        }
    }
    if (tid == 0) row_ptr[N] = nnz;
}

__global__ void scatter_kernel(const int* __restrict__ rows,
                               const int* __restrict__ cols,
                               const float* __restrict__ vals,
                               int* woff, int2* edges, int nnz) {
    int e = (blockIdx.x * blockDim.x + threadIdx.x) * 4;
    if (e + 4 <= nnz) {
        int4   r = *(const int4*)(rows + e);
        int4   c = *(const int4*)(cols + e);
        float4 v = *(const float4*)(vals + e);
        int p0 = atomicAdd(&woff[r.x], 1);
        int p1 = atomicAdd(&woff[r.y], 1);
        int p2 = atomicAdd(&woff[r.z], 1);
        int p3 = atomicAdd(&woff[r.w], 1);
        edges[p0] = make_int2(c.x, __float_as_int(v.x));
        edges[p1] = make_int2(c.y, __float_as_int(v.y));
        edges[p2] = make_int2(c.z, __float_as_int(v.z));
        edges[p3] = make_int2(c.w, __float_as_int(v.w));
    } else {
        for (int k = e; k < nnz; k++) {
            int p = atomicAdd(&woff[rows[k]], 1);
            edges[p] = make_int2(cols[k], __float_as_int(vals[k]));
        }
    }
}

// ---------------- fp32 -> fp16 conversion (for the initial m) ----------------
__global__ void f2h_kernel(const float* __restrict__ src, __half* __restrict__ dst,
                           int n) {
    int i = blockIdx.x * blockDim.x + threadIdx.x;
    if (i < n) {
        float2 v = ((const float2*)src)[i];
        ((__half2*)dst)[i] = __floats2half2_rn(v.x, v.y);
    }
}

// ---------------- SpMM: warp per row, CSR, fp16 gather, 4-edge MLP ---------
__global__ void spmm16_kernel(const __half* __restrict__ H,
                              const int* __restrict__ row_ptr,
                              const int2* __restrict__ edges,
                              float* __restrict__ Hn, int N) {
    int warp = (blockIdx.x * blockDim.x + threadIdx.x) >> 5;
    int lane = threadIdx.x & 31;
    if (warp >= N) return;
    int start = row_ptr[warp];
    int end   = row_ptr[warp + 1];

    float acc[8];
    #pragma unroll
    for (int i = 0; i < 8; i++) acc[i] = 0.f;

    auto accum = [&](uint4 raw, float val) {
        const __half2* hh = (const __half2*)&raw;
        float2 f0 = __half22float2(hh[0]);
        float2 f1 = __half22float2(hh[1]);
        float2 f2 = __half22float2(hh[2]);
        float2 f3 = __half22float2(hh[3]);
        acc[0] += val * f0.x; acc[1] += val * f0.y;
        acc[2] += val * f1.x; acc[3] += val * f1.y;
        acc[4] += val * f2.x; acc[5] += val * f2.y;
        acc[6] += val * f3.x; acc[7] += val * f3.y;
    };

    for (int e0 = start; e0 < end; e0 += 32) {
        int idx = e0 + lane;
        int2 ed = make_int2(0, 0);
        if (idx < end) ed = edges[idx];
        int cnt = min(32, end - e0);
        int j = 0;
        for (; j + 4 <= cnt; j += 4) {
            int   c0 = __shfl_sync(0xffffffffu, ed.x, j + 0);
            int   c1 = __shfl_sync(0xffffffffu, ed.x, j + 1);
            int   c2 = __shfl_sync(0xffffffffu, ed.x, j + 2);
            int   c3 = __shfl_sync(0xffffffffu, ed.x, j + 3);
            float v0 = __int_as_float(__shfl_sync(0xffffffffu, ed.y, j + 0));
            float v1 = __int_as_float(__shfl_sync(0xffffffffu, ed.y, j + 1));
            float v2 = __int_as_float(__shfl_sync(0xffffffffu, ed.y, j + 2));
            float v3 = __int_as_float(__shfl_sync(0xffffffffu, ed.y, j + 3));
            uint4 r0 = ((const uint4*)(H + (size_t)c0 * DIMC))[lane];
            uint4 r1 = ((const uint4*)(H + (size_t)c1 * DIMC))[lane];
            uint4 r2 = ((const uint4*)(H + (size_t)c2 * DIMC))[lane];
            uint4 r3 = ((const uint4*)(H + (size_t)c3 * DIMC))[lane];
            accum(r0, v0);
            accum(r1, v1);
            accum(r2, v2);
            accum(r3, v3);
        }
        for (; j < cnt; j++) {
            int   col = __shfl_sync(0xffffffffu, ed.x, j);
            float val = __int_as_float(__shfl_sync(0xffffffffu, ed.y, j));
            uint4 raw = ((const uint4*)(H + (size_t)col * DIMC))[lane];
            accum(raw, val);
        }
    }
    float4* out = (float4*)(Hn + (size_t)warp * DIMC);
    out[lane * 2 + 0] = make_float4(acc[0], acc[1], acc[2], acc[3]);
    out[lane * 2 + 1] = make_float4(acc[4], acc[5], acc[6], acc[7]);
}

// ---------------- tf32 tensor-core GEMM, K=256 half (R8 shape) ----------------
// out[M,256] = A@W^T (+ partial + bn + bs, + ELU) ; optional fp16 shadow store.
// Block tile 128x128, 4 warps (2x2), warp 64x64, BK=16, cp.async dbl-buffered.
#define GSTR 20   // smem row stride in words (16 k + 4 pad) -> conflict-free frags

__device__ __forceinline__ unsigned f2tf32(float x) {
    unsigned r;
    asm("cvt.rna.tf32.f32 %0, %1;" : "=r"(r) : "f"(x));
    return r;
}

__global__ __launch_bounds__(128)
void gemm256_kernel(const float* __restrict__ A, const float* __restrict__ W,
                    const float* __restrict__ partial,
                    const float* __restrict__ bn, const float* __restrict__ bs,
                    float* __restrict__ out, __half* __restrict__ out16,
                    int M, int doElu) {
    __shared__ float As[2][128 * GSTR];
    __shared__ float Bs[2][128 * GSTR];

    int tid  = threadIdx.x;
    int lane = tid & 31;
    int wid  = tid >> 5;
    int grp  = lane >> 2;
    int tig  = lane & 3;
    int warpM = wid >> 1;
    int warpN = wid & 1;
    int rowBase = blockIdx.x * 128;
    int colBase = blockIdx.y * 128;

    int lf = tid & 3;
    int lr = tid >> 2;

    float c[4][8][4];
    #pragma unroll
    for (int mi = 0; mi < 4; mi++)
        #pragma unroll
        for (int ni = 0; ni < 8; ni++)
            #pragma unroll
            for (int r = 0; r < 4; r++) c[mi][ni][r] = 0.f;

    auto issue = [&](int it) {
        int kOff = it * 16;
        int st = it & 1;
        #pragma unroll
        for (int i = 0; i < 4; i++) {
            int row = lr + 32 * i;
            int grow = rowBase + row;
            int ok = (grow < M);
            const float* asrc = A + (size_t)(ok ? grow : 0) * DIMC + kOff + lf * 4;
            unsigned adst = (unsigned)__cvta_generic_to_shared(&As[st][row * GSTR + lf * 4]);
            int asz = ok ? 16 : 0;
            asm volatile("cp.async.cg.shared.global [%0], [%1], 16, %2;\n"
                         :: "r"(adst), "l"(asrc), "r"(asz));
            const float* bsrc = W + (size_t)(colBase + row) * DIMC + kOff + lf * 4;
            unsigned bdst = (unsigned)__cvta_generic_to_shared(&Bs[st][row * GSTR + lf * 4]);
            asm volatile("cp.async.cg.shared.global [%0], [%1], 16, %2;\n"
                         :: "r"(bdst), "l"(bsrc), "r"(16));
        }
        asm volatile("cp.async.commit_group;\n");
    };

    issue(0);

    for (int it = 0; it < 16; it++) {
        if (it + 1 < 16) {
            issue(it + 1);
            asm volatile("cp.async.wait_group 1;\n");
        } else {
            asm volatile("cp.async.wait_group 0;\n");
        }
        __syncthreads();

        int st = it & 1;
        #pragma unroll
        for (int kk = 0; kk < 2; kk++) {
            unsigned a[4][4], b[8][2];
            int k = kk * 8 + tig;
            #pragma unroll
            for (int mi = 0; mi < 4; mi++) {
                int m0 = warpM * 64 + mi * 16 + grp;
                a[mi][0] = f2tf32(As[st][m0 * GSTR + k]);
                a[mi][1] = f2tf32(As[st][(m0 + 8) * GSTR + k]);
                a[mi][2] = f2tf32(As[st][m0 * GSTR + k + 4]);
                a[mi][3] = f2tf32(As[st][(m0 + 8) * GSTR + k + 4]);
            }
            #pragma unroll
            for (int ni = 0; ni < 8; ni++) {
                int n0 = warpN * 64 + ni * 8 + grp;
                b[ni][0] = f2tf32(Bs[st][n0 * GSTR + k]);
                b[ni][1] = f2tf32(Bs[st][n0 * GSTR + k + 4]);
            }
            #pragma unroll
            for (int mi = 0; mi < 4; mi++)
                #pragma unroll
                for (int ni = 0; ni < 8; ni++) {
                    asm volatile(
                        "mma.sync.aligned.m16n8k8.row.col.f32.tf32.tf32.f32 "
                        "{%0,%1,%2,%3}, {%4,%5,%6,%7}, {%8,%9}, {%0,%1,%2,%3};\n"
                        : "+f"(c[mi][ni][0]), "+f"(c[mi][ni][1]),
                          "+f"(c[mi][ni][2]), "+f"(c[mi][ni][3])
                        : "r"(a[mi][0]), "r"(a[mi][1]), "r"(a[mi][2]), "r"(a[mi][3]),
                          "r"(b[ni][0]), "r"(b[ni][1]));
                }
        }
        __syncthreads();
    }

    // epilogue
    #pragma unroll
    for (int mi = 0; mi < 4; mi++) {
        #pragma unroll
        for (int r = 0; r < 2; r++) {
            int grow = rowBase + warpM * 64 + mi * 16 + grp + r * 8;
            if (grow >= M) continue;
            #pragma unroll
            for (int ni = 0; ni < 8; ni++) {
                int gcol = colBase + warpN * 64 + ni * 8 + tig * 2;
                float v0 = c[mi][ni][r * 2 + 0];
                float v1 = c[mi][ni][r * 2 + 1];
                if (partial) {
                    float2 p = *(const float2*)(partial + (size_t)grow * DIMC + gcol);
                    v0 += p.x + bn[gcol]     + bs[gcol];
                    v1 += p.y + bn[gcol + 1] + bs[gcol + 1];
                }
                if (doElu) {
                    if (v0 < 0.f) v0 = expm1f(v0);
                    if (v1 < 0.f) v1 = expm1f(v1);
                }
                *(float2*)(out + (size_t)grow * DIMC + gcol) = make_float2(v0, v1);
                if (out16)
                    *(__half2*)(out16 + (size_t)grow * DIMC + gcol) =
                        __floats2half2_rn(v0, v1);
            }
        }
    }
}

// ---------------- launch ----------------
extern "C" void kernel_launch(void* const* d_in, const int* in_sizes, int n_in,
                              void* d_out, int out_size) {
    const float* m    = (const float*)d_in[0];
    const float* vals = (const float*)d_in[1];
    const float* Wn   = (const float*)d_in[2];
    const float* bn   = (const float*)d_in[3];
    const float* Ws   = (const float*)d_in[4];
    const float* bs   = (const float*)d_in[5];
    const int*   rows = (const int*)d_in[6];
    const int*   cols = (const int*)d_in[7];

    int N    = in_sizes[0] / DIMC;
    int nnz  = in_sizes[1];
    int hops = in_sizes[2] / (DIMC * DIMC);

    float *Hn, *P, *HA, *HB;
    __half* H16;
    int *cnt, *rowptr, *woff;
    int2* edges;
    cudaGetSymbolAddress((void**)&Hn,     g_Hn);
    cudaGetSymbolAddress((void**)&P,      g_P);
    cudaGetSymbolAddress((void**)&HA,     g_HA);
    cudaGetSymbolAddress((void**)&HB,     g_HB);
    cudaGetSymbolAddress((void**)&H16,    g_H16);
    cudaGetSymbolAddress((void**)&edges,  g_edges);
    cudaGetSymbolAddress((void**)&cnt,    g_cnt);
    cudaGetSymbolAddress((void**)&rowptr, g_rowptr);
    cudaGetSymbolAddress((void**)&woff,   g_woff);

    // fork stream + events (graph fork-join capture pattern; no device allocs)
    cudaStream_t sB = 0;
    if (cudaStreamCreateWithFlags(&sB, cudaStreamNonBlocking) != cudaSuccess)
        sB = 0;   // fallback: everything on origin stream (order still valid)
    cudaEvent_t evFork, evF, evS0, evS1, evS2, evH1, evH2;
    cudaEventCreateWithFlags(&evFork, cudaEventDisableTiming);
    cudaEventCreateWithFlags(&evF,    cudaEventDisableTiming);
    cudaEventCreateWithFlags(&evS0,   cudaEventDisableTiming);
    cudaEventCreateWithFlags(&evS1,   cudaEventDisableTiming);
    cudaEventCreateWithFlags(&evS2,   cudaEventDisableTiming);
    cudaEventCreateWithFlags(&evH1,   cudaEventDisableTiming);
    cudaEventCreateWithFlags(&evH2,   cudaEventDisableTiming);
    cudaEvent_t evS[3] = {evS0, evS1, evS2};
    cudaEvent_t evH[3] = {evFork, evH1, evH2};

    dim3 ggrid((N + 127) / 128, DIMC / 128);
    int spmm_blocks = (N * 32 + 255) / 256;
    int e4 = (nnz + 3) / 4;
    int nh2 = N * DIMC / 2;
    float* out0 = (float*)d_out;

    // fork
    cudaEventRecord(evFork, 0);
    cudaStreamWaitEvent(sB, evFork, 0);

    // stream B: f2h(m) then Hs-GEMM hop0 (m @ Ws0 -> P)
    f2h_kernel<<<(nh2 + 255) / 256, 256, 0, sB>>>(m, H16, nh2);
    cudaEventRecord(evF, sB);
    gemm256_kernel<<<ggrid, 128, 0, sB>>>(m, Ws, nullptr, nullptr, nullptr,
                                          P, nullptr, N, 0);
    cudaEventRecord(evS[0], sB);

    // origin stream: CSR build
    zero_cnt_kernel<<<(N + 255) / 256, 256>>>(cnt, N);
    hist_kernel<<<(e4 + 255) / 256, 256>>>(rows, cnt, nnz);
    scan_kernel<<<1, 1024>>>(cnt, rowptr, woff, N, nnz);
    scatter_kernel<<<(e4 + 255) / 256, 256>>>(rows, cols, vals, woff, edges, nnz);
    cudaStreamWaitEvent(0, evF, 0);   // H16 ready for SpMM0

    const float* Hcur = m;
    for (int i = 0; i < hops; i++) {
        spmm16_kernel<<<spmm_blocks, 256>>>(H16, rowptr, edges, Hn, N);
        cudaStreamWaitEvent(0, evS[i], 0);        // partial P ready
        int last = (i == hops - 1);
        float* dst = last ? out0 : (i == 0 ? HA : HB);
        gemm256_kernel<<<ggrid, 128>>>(Hn, Wn + (size_t)i * DIMC * DIMC,
                                       P,
                                       bn + (size_t)i * DIMC,
                                       bs + (size_t)i * DIMC,
                                       dst, last ? (__half*)nullptr : H16,
                                       N, !last);
        if (!last) {
            cudaEventRecord(evH[i + 1], 0);
            cudaStreamWaitEvent(sB, evH[i + 1], 0);   // H_{i+1} ready
            gemm256_kernel<<<ggrid, 128, 0, sB>>>(dst,
                                       Ws + (size_t)(i + 1) * DIMC * DIMC,
                                       nullptr, nullptr, nullptr,
                                       P, nullptr, N, 0);
            cudaEventRecord(evS[i + 1], sB);
        }
        Hcur = dst;
    }
    // sB fully rejoined: last wait on evS[hops-1] precedes final GEMM above.
}

// round 12
// speedup vs baseline: 1.1834x; 1.1476x over previous
#include <cuda_runtime.h>
#include <cuda_fp16.h>

// ---------------- constants (match problem shape) ----------------
#define NMAX      100000
#define NNZMAX    3200000
#define DIMC      256

// ---------------- device scratch (no allocations allowed) ----------------
__device__ static __half g_Hn16[NMAX * DIMC];  // SpMM result per hop (fp16)
__device__ static __half g_H16a[NMAX * DIMC];  // H ping (fp16)
__device__ static __half g_H16b[NMAX * DIMC];  // H pong (fp16)
__device__ static int2   g_edges[NNZMAX];      // CSR: (col, val-as-bits) sorted by row
__device__ static int    g_cnt[NMAX];
__device__ static int    g_rowptr[NMAX + 1];
__device__ static int    g_woff[NMAX];

// ---------------- CSR build ----------------
__global__ void zero_cnt_kernel(int* cnt, int N) {
    int i = blockIdx.x * blockDim.x + threadIdx.x;
    if (i < N) cnt[i] = 0;
}

// 4 edges per thread: vector load + 4 independent atomics (MLP)
__global__ void hist_kernel(const int* __restrict__ rows, int* cnt, int nnz) {
    int e = (blockIdx.x * blockDim.x + threadIdx.x) * 4;
    if (e + 4 <= nnz) {
        int4 r = *(const int4*)(rows + e);
        atomicAdd(&cnt[r.x], 1);
        atomicAdd(&cnt[r.y], 1);
        atomicAdd(&cnt[r.z], 1);
        atomicAdd(&cnt[r.w], 1);
    } else {
        for (int k = e; k < nnz; k++) atomicAdd(&cnt[rows[k]], 1);
    }
}

// single-block exclusive scan over N counts (1024 threads, sequential chunks)
__global__ void scan_kernel(const int* __restrict__ cnt, int* row_ptr, int* woff,
                            int N, int nnz) {
    __shared__ int wsum[32];
    int tid = threadIdx.x;
    int CH = (N + 1023) / 1024;
    int base = tid * CH;
    int s = 0;
    for (int j = 0; j < CH; j++) {
        int i = base + j;
        if (i < N) s += cnt[i];
    }
    int v = s;
    #pragma unroll
    for (int d = 1; d < 32; d <<= 1) {
        int n = __shfl_up_sync(0xffffffffu, v, d);
        if ((tid & 31) >= d) v += n;
    }
    if ((tid & 31) == 31) wsum[tid >> 5] = v;
    __syncthreads();
    if (tid < 32) {
        int w = wsum[tid];
        #pragma unroll
        for (int d = 1; d < 32; d <<= 1) {
            int n = __shfl_up_sync(0xffffffffu, w, d);
            if (tid >= d) w += n;
        }
        wsum[tid] = w;
    }
    __syncthreads();
    int warp = tid >> 5;
    int excl = (v - s) + (warp > 0 ? wsum[warp - 1] : 0);
    int run = excl;
    for (int j = 0; j < CH; j++) {
        int i = base + j;
        if (i < N) {
            row_ptr[i] = run;
            woff[i]    = run;
            run += cnt[i];
        }
    }
    if (tid == 0) row_ptr[N] = nnz;
}

// 4 edges per thread: vector loads, 4 independent atomic+store pairs
__global__ void scatter_kernel(const int* __restrict__ rows,
                               const int* __restrict__ cols,
                               const float* __restrict__ vals,
                               int* woff, int2* edges, int nnz) {
    int e = (blockIdx.x * blockDim.x + threadIdx.x) * 4;
    if (e + 4 <= nnz) {
        int4   r = *(const int4*)(rows + e);
        int4   c = *(const int4*)(cols + e);
        float4 v = *(const float4*)(vals + e);
        int p0 = atomicAdd(&woff[r.x], 1);
        int p1 = atomicAdd(&woff[r.y], 1);
        int p2 = atomicAdd(&woff[r.z], 1);
        int p3 = atomicAdd(&woff[r.w], 1);
        edges[p0] = make_int2(c.x, __float_as_int(v.x));
        edges[p1] = make_int2(c.y, __float_as_int(v.y));
        edges[p2] = make_int2(c.z, __float_as_int(v.z));
        edges[p3] = make_int2(c.w, __float_as_int(v.w));
    } else {
        for (int k = e; k < nnz; k++) {
            int p = atomicAdd(&woff[rows[k]], 1);
            edges[p] = make_int2(cols[k], __float_as_int(vals[k]));
        }
    }
}

// ---------------- fp32 -> fp16 conversion (for the initial m) ----------------
__global__ void f2h_kernel(const float* __restrict__ src, __half* __restrict__ dst,
                           int n) {  // n = total elems / 2
    int i = blockIdx.x * blockDim.x + threadIdx.x;
    if (i < n) {
        float2 v = ((const float2*)src)[i];
        ((__half2*)dst)[i] = __floats2half2_rn(v.x, v.y);
    }
}

// ---------------- SpMM: warp per row, CSR, fp16 gather, fp16 out, 4-edge MLP
__global__ void spmm16_kernel(const __half* __restrict__ H,
                              const int* __restrict__ row_ptr,
                              const int2* __restrict__ edges,
                              __half* __restrict__ Hn, int N) {
    int warp = (blockIdx.x * blockDim.x + threadIdx.x) >> 5;
    int lane = threadIdx.x & 31;
    if (warp >= N) return;
    int start = row_ptr[warp];
    int end   = row_ptr[warp + 1];

    float acc[8];
    #pragma unroll
    for (int i = 0; i < 8; i++) acc[i] = 0.f;

    auto accum = [&](uint4 raw, float val) {
        const __half2* hh = (const __half2*)&raw;
        float2 f0 = __half22float2(hh[0]);
        float2 f1 = __half22float2(hh[1]);
        float2 f2 = __half22float2(hh[2]);
        float2 f3 = __half22float2(hh[3]);
        acc[0] += val * f0.x; acc[1] += val * f0.y;
        acc[2] += val * f1.x; acc[3] += val * f1.y;
        acc[4] += val * f2.x; acc[5] += val * f2.y;
        acc[6] += val * f3.x; acc[7] += val * f3.y;
    };

    for (int e0 = start; e0 < end; e0 += 32) {
        int idx = e0 + lane;
        int2 ed = make_int2(0, 0);
        if (idx < end) ed = edges[idx];
        int cnt = min(32, end - e0);
        int j = 0;
        for (; j + 4 <= cnt; j += 4) {
            int   c0 = __shfl_sync(0xffffffffu, ed.x, j + 0);
            int   c1 = __shfl_sync(0xffffffffu, ed.x, j + 1);
            int   c2 = __shfl_sync(0xffffffffu, ed.x, j + 2);
            int   c3 = __shfl_sync(0xffffffffu, ed.x, j + 3);
            float v0 = __int_as_float(__shfl_sync(0xffffffffu, ed.y, j + 0));
            float v1 = __int_as_float(__shfl_sync(0xffffffffu, ed.y, j + 1));
            float v2 = __int_as_float(__shfl_sync(0xffffffffu, ed.y, j + 2));
            float v3 = __int_as_float(__shfl_sync(0xffffffffu, ed.y, j + 3));
            uint4 r0 = ((const uint4*)(H + (size_t)c0 * DIMC))[lane];
            uint4 r1 = ((const uint4*)(H + (size_t)c1 * DIMC))[lane];
            uint4 r2 = ((const uint4*)(H + (size_t)c2 * DIMC))[lane];
            uint4 r3 = ((const uint4*)(H + (size_t)c3 * DIMC))[lane];
            accum(r0, v0);
            accum(r1, v1);
            accum(r2, v2);
            accum(r3, v3);
        }
        for (; j < cnt; j++) {
            int   col = __shfl_sync(0xffffffffu, ed.x, j);
            float val = __int_as_float(__shfl_sync(0xffffffffu, ed.y, j));
            uint4 raw = ((const uint4*)(H + (size_t)col * DIMC))[lane];
            accum(raw, val);
        }
    }
    __half2 o[4];
    o[0] = __floats2half2_rn(acc[0], acc[1]);
    o[1] = __floats2half2_rn(acc[2], acc[3]);
    o[2] = __floats2half2_rn(acc[4], acc[5]);
    o[3] = __floats2half2_rn(acc[6], acc[7]);
    ((uint4*)(Hn + (size_t)warp * DIMC))[lane] = *(uint4*)o;
}

// ---------------- tf32 tensor-core GEMM, fp16 A operand ----------------
// out[M,256] = Hn16@Wn^T + Hc16@Ws^T + (bn+bs), optional ELU.
// K=512 logical (k<256 -> Hn16/Wn, else Hc16/Ws). R8 shape: block 128x128,
// 4 warps (2x2), warp 64x64, BK=16, cp.async double-buffered.
// A in fp16 (exact in tf32: fp16 10-bit mantissa \subset tf32), W fp32->tf32.
// Writes fp32 out (last hop) OR fp16 out16 (intermediate hops).
#define GSTR 20   // B smem row stride (floats): 16 k + 4 pad
#define ASTR 24   // A smem row stride (halves): 16 k + 8 pad

__device__ __forceinline__ unsigned f2tf32(float x) {
    unsigned r;
    asm("cvt.rna.tf32.f32 %0, %1;" : "=r"(r) : "f"(x));
    return r;
}
__device__ __forceinline__ unsigned h2tf32(__half h) {
    return __float_as_uint(__half2float(h));   // exact: fp16 mantissa fits tf32
}

__global__ __launch_bounds__(128)
void gemm_tf32_kernel(const __half* __restrict__ Hn, const __half* __restrict__ Hc,
                      const float* __restrict__ Wn, const float* __restrict__ Ws,
                      const float* __restrict__ bn, const float* __restrict__ bs,
                      float* __restrict__ out, __half* __restrict__ out16,
                      int M, int doElu) {
    __shared__ __half As[2][128 * ASTR];
    __shared__ float  Bs[2][128 * GSTR];

    int tid  = threadIdx.x;
    int lane = tid & 31;
    int wid  = tid >> 5;
    int grp  = lane >> 2;       // 0..7
    int tig  = lane & 3;        // 0..3
    int warpM = wid >> 1;       // 0..1
    int warpN = wid & 1;        // 0..1
    int rowBase = blockIdx.x * 128;
    int colBase = blockIdx.y * 128;

    int lf = tid & 3;           // B k-float4 slot
    int lr = tid >> 2;          // B row base (0..31)

    float c[4][8][4];
    #pragma unroll
    for (int mi = 0; mi < 4; mi++)
        #pragma unroll
        for (int ni = 0; ni < 8; ni++)
            #pragma unroll
            for (int r = 0; r < 4; r++) c[mi][ni][r] = 0.f;

    // issue cp.async loads for k-slab `it` into stage it&1
    auto issue = [&](int it) {
        int k0 = it * 16;
        const __half* Asrc = (k0 < 256) ? Hn : Hc;
        const float*  Wsrc = (k0 < 256) ? Wn : Ws;
        int kOff = k0 & 255;
        int st = it & 1;
        // A tile: 128 rows x 16 halves = 256 x 16B chunks, 2 per thread
        #pragma unroll
        for (int i = 0; i < 2; i++) {
            int idx = tid + i * 128;
            int row = idx >> 1;
            int c8  = (idx & 1) * 8;
            int grow = rowBase + row;
            int ok = (grow < M);
            const __half* asrc = Asrc + (size_t)(ok ? grow : 0) * DIMC + kOff + c8;
            unsigned adst = (unsigned)__cvta_generic_to_shared(&As[st][row * ASTR + c8]);
            int asz = ok ? 16 : 0;
            asm volatile("cp.async.cg.shared.global [%0], [%1], 16, %2;\n"
                         :: "r"(adst), "l"(asrc), "r"(asz));
        }
        // B tile: 128 rows x 16 floats = 512 x 16B chunks, 4 per thread
        #pragma unroll
        for (int i = 0; i < 4; i++) {
            int row = lr + 32 * i;
            const float* bsrc = Wsrc + (size_t)(colBase + row) * DIMC + kOff + lf * 4;
            unsigned bdst = (unsigned)__cvta_generic_to_shared(&Bs[st][row * GSTR + lf * 4]);
            asm volatile("cp.async.cg.shared.global [%0], [%1], 16, %2;\n"
                         :: "r"(bdst), "l"(bsrc), "r"(16));
        }
        asm volatile("cp.async.commit_group;\n");
    };

    issue(0);

    for (int it = 0; it < 32; it++) {
        if (it + 1 < 32) {
            issue(it + 1);
            asm volatile("cp.async.wait_group 1;\n");
        } else {
            asm volatile("cp.async.wait_group 0;\n");
        }
        __syncthreads();

        int st = it & 1;
        #pragma unroll
        for (int kk = 0; kk < 2; kk++) {
            unsigned a[4][4], b[8][2];
            int k = kk * 8 + tig;
            #pragma unroll
            for (int mi = 0; mi < 4; mi++) {
                int m0 = warpM * 64 + mi * 16 + grp;
                a[mi][0] = h2tf32(As[st][m0 * ASTR + k]);
                a[mi][1] = h2tf32(As[st][(m0 + 8) * ASTR + k]);
                a[mi][2] = h2tf32(As[st][m0 * ASTR + k + 4]);
                a[mi][3] = h2tf32(As[st][(m0 + 8) * ASTR + k + 4]);
            }
            #pragma unroll
            for (int ni = 0; ni < 8; ni++) {
                int n0 = warpN * 64 + ni * 8 + grp;
                b[ni][0] = f2tf32(Bs[st][n0 * GSTR + k]);
                b[ni][1] = f2tf32(Bs[st][n0 * GSTR + k + 4]);
            }
            #pragma unroll
            for (int mi = 0; mi < 4; mi++)
                #pragma unroll
                for (int ni = 0; ni < 8; ni++) {
                    asm volatile(
                        "mma.sync.aligned.m16n8k8.row.col.f32.tf32.tf32.f32 "
                        "{%0,%1,%2,%3}, {%4,%5,%6,%7}, {%8,%9}, {%0,%1,%2,%3};\n"
                        : "+f"(c[mi][ni][0]), "+f"(c[mi][ni][1]),
                          "+f"(c[mi][ni][2]), "+f"(c[mi][ni][3])
                        : "r"(a[mi][0]), "r"(a[mi][1]), "r"(a[mi][2]), "r"(a[mi][3]),
                          "r"(b[ni][0]), "r"(b[ni][1]));
                }
        }
        __syncthreads();
    }

    // epilogue: bias + optional ELU; fp32 out (last hop) OR fp16 out16
    #pragma unroll
    for (int mi = 0; mi < 4; mi++) {
        #pragma unroll
        for (int r = 0; r < 2; r++) {
            int grow = rowBase + warpM * 64 + mi * 16 + grp + r * 8;
            if (grow >= M) continue;
            #pragma unroll
            for (int ni = 0; ni < 8; ni++) {
                int gcol = colBase + warpN * 64 + ni * 8 + tig * 2;
                float v0 = c[mi][ni][r * 2 + 0] + bn[gcol]     + bs[gcol];
                float v1 = c[mi][ni][r * 2 + 1] + bn[gcol + 1] + bs[gcol + 1];
                if (doElu) {
                    if (v0 < 0.f) v0 = expm1f(v0);
                    if (v1 < 0.f) v1 = expm1f(v1);
                }
                if (out)
                    *(float2*)(out + (size_t)grow * DIMC + gcol) = make_float2(v0, v1);
                else
                    *(__half2*)(out16 + (size_t)grow * DIMC + gcol) =
                        __floats2half2_rn(v0, v1);
            }
        }
    }
}

// ---------------- launch ----------------
extern "C" void kernel_launch(void* const* d_in, const int* in_sizes, int n_in,
                              void* d_out, int out_size) {
    const float* m    = (const float*)d_in[0];
    const float* vals = (const float*)d_in[1];
    const float* Wn   = (const float*)d_in[2];
    const float* bn   = (const float*)d_in[3];
    const float* Ws   = (const float*)d_in[4];
    const float* bs   = (const float*)d_in[5];
    const int*   rows = (const int*)d_in[6];   // int32: JAX default x64-disabled
    const int*   cols = (const int*)d_in[7];

    int N    = in_sizes[0] / DIMC;
    int nnz  = in_sizes[1];
    int hops = in_sizes[2] / (DIMC * DIMC);

    __half *Hn16, *H16a, *H16b;
    int *cnt, *rowptr, *woff;
    int2* edges;
    cudaGetSymbolAddress((void**)&Hn16,   g_Hn16);
    cudaGetSymbolAddress((void**)&H16a,   g_H16a);
    cudaGetSymbolAddress((void**)&H16b,   g_H16b);
    cudaGetSymbolAddress((void**)&edges,  g_edges);
    cudaGetSymbolAddress((void**)&cnt,    g_cnt);
    cudaGetSymbolAddress((void**)&rowptr, g_rowptr);
    cudaGetSymbolAddress((void**)&woff,   g_woff);

    // --- build CSR once, reuse across hops ---
    zero_cnt_kernel<<<(N + 255) / 256, 256>>>(cnt, N);
    int e4 = (nnz + 3) / 4;
    hist_kernel<<<(e4 + 255) / 256, 256>>>(rows, cnt, nnz);
    scan_kernel<<<1, 1024>>>(cnt, rowptr, woff, N, nnz);
    scatter_kernel<<<(e4 + 255) / 256, 256>>>(rows, cols, vals, woff, edges, nnz);

    // --- fp16 shadow of initial H ---
    int nh2 = N * DIMC / 2;
    f2h_kernel<<<(nh2 + 255) / 256, 256>>>(m, H16a, nh2);

    // --- hop loop ---
    float* out0 = (float*)d_out;
    int spmm_blocks = (N * 32 + 255) / 256;     // warp per row
    dim3 ggrid((N + 127) / 128, DIMC / 128);

    __half* Hcur  = H16a;
    __half* Hnext = H16b;
    for (int i = 0; i < hops; i++) {
        spmm16_kernel<<<spmm_blocks, 256>>>(Hcur, rowptr, edges, Hn16, N);
        int last = (i == hops - 1);
        gemm_tf32_kernel<<<ggrid, 128>>>(Hn16, Hcur,
                                         Wn + (size_t)i * DIMC * DIMC,
                                         Ws + (size_t)i * DIMC * DIMC,
                                         bn + (size_t)i * DIMC,
                                         bs + (size_t)i * DIMC,
                                         last ? out0 : nullptr,
                                         last ? nullptr : Hnext,
                                         N, !last);
        __half* t = Hcur; Hcur = Hnext; Hnext = t;
    }
}